// round 11
// baseline (speedup 1.0000x reference)
#include <cuda_runtime.h>
#include <cstddef>

#define NN   100000
#define NE   3200000
#define FIN  10
#define HID  30
#define NCLS 4
#define S1   16   // layer-1 fp32 row stride (64B; 2 rows per 128B line)
#define S2   32   // layer-2 / accumulator fp32 row stride (128B = 1 line)

#define SCAN_BS 512
#define SCAN_NB ((NN + SCAN_BS - 1) / SCAN_BS)   // 196

// ---------------- scratch (static device globals) ---------------------------
__device__ __align__(16) float g_deg[NN];
__device__ __align__(16) int   g_cnt[NN];
__device__ __align__(16) int   g_rs[NN + 1];
__device__ __align__(16) int   g_cur[NN];
__device__ __align__(16) int   g_bsum[SCAN_NB];
__device__ __align__(16) int   g_boff[SCAN_NB];
__device__ __align__(16) int2  g_recs[NE];       // {src, norm bits} sorted by dst
__device__ __align__(16) float g_T0[NN * S1];
__device__ __align__(16) float g_T1[NN * S1];
__device__ __align__(16) float g_T2[NN * S1];
__device__ __align__(16) float g_A2[NN * S2];
__device__ __align__(16) float g_B2[NN * S2];
__device__ __align__(16) float g_C2[NN * S2];
__device__ __align__(16) float g_O1[NN * S2];
__device__ __align__(16) float g_O2[NN * S2];

// ---------------- degree + histogram -----------------------------------------
__global__ void k_zero() {
    int i = blockIdx.x * blockDim.x + threadIdx.x;
    if (i < NN) { g_deg[i] = 0.f; g_cnt[i] = 0; }
}

__global__ void k_deg(const int* __restrict__ src, const int* __restrict__ dst,
                      const float* __restrict__ w) {
    int e = blockIdx.x * blockDim.x + threadIdx.x;
    if (e >= NE) return;
    int s = src[e], d = dst[e];
    if (s != d) atomicAdd(&g_deg[s], w[e]);
    atomicAdd(&g_cnt[d], 1);
}

// ---------------- CSR build: 2-level exclusive scan --------------------------
__global__ void k_scan1() {
    __shared__ int sh[SCAN_BS];
    int tid = threadIdx.x;
    int i = blockIdx.x * SCAN_BS + tid;
    int v = (i < NN) ? g_cnt[i] : 0;
    sh[tid] = v;
    __syncthreads();
#pragma unroll
    for (int ofs = 1; ofs < SCAN_BS; ofs <<= 1) {
        int t = (tid >= ofs) ? sh[tid - ofs] : 0;
        __syncthreads();
        sh[tid] += t;
        __syncthreads();
    }
    if (i < NN) g_rs[i] = sh[tid] - v;
    if (tid == SCAN_BS - 1) g_bsum[blockIdx.x] = sh[tid];
}

__global__ void k_scan2() {
    __shared__ int sh[256];
    int tid = threadIdx.x;
    int v = (tid < SCAN_NB) ? g_bsum[tid] : 0;
    sh[tid] = v;
    __syncthreads();
#pragma unroll
    for (int ofs = 1; ofs < 256; ofs <<= 1) {
        int t = (tid >= ofs) ? sh[tid - ofs] : 0;
        __syncthreads();
        sh[tid] += t;
        __syncthreads();
    }
    if (tid < SCAN_NB) g_boff[tid] = sh[tid] - v;
}

__global__ void k_scan3() {
    int i = blockIdx.x * blockDim.x + threadIdx.x;
    if (i < NN) {
        int r = g_rs[i] + g_boff[i / SCAN_BS];
        g_rs[i] = r;
        g_cur[i] = r;
    }
    if (i == 0) g_rs[NN] = NE;
}

// ---------------- fused norm + record scatter --------------------------------
__global__ void k_normbuild(const int* __restrict__ src, const int* __restrict__ dst,
                            const float* __restrict__ w) {
    int e = blockIdx.x * blockDim.x + threadIdx.x;
    if (e >= NE) return;
    int s = src[e], d = dst[e];
    float we = (s == d) ? 0.f : w[e];
    float ds = g_deg[s], dd = g_deg[d];
    float is = (ds > 0.f) ? rsqrtf(ds) : 0.f;
    float id = (dd > 0.f) ? rsqrtf(dd) : 0.f;
    float norm = -is * we * id;
    int p = atomicAdd(&g_cur[d], 1);
    g_recs[p] = make_int2(s, __float_as_int(norm));
}

// ---------------- layer 1 init: T0 = pad16(x), O1 = x @ W1[0] ----------------
__global__ void k_l1_init(const float* __restrict__ x, const float* __restrict__ W0) {
    __shared__ __align__(16) float sWp[FIN * 32];
    for (int i = threadIdx.x; i < FIN * 32; i += blockDim.x) {
        int r = i >> 5, c = i & 31;
        sWp[i] = (c < HID) ? W0[r * HID + c] : 0.f;
    }
    __syncthreads();
    int n = blockIdx.x * blockDim.x + threadIdx.x;
    if (n >= NN) return;
    float t[FIN];
    const float* xr = x + (size_t)n * FIN;
#pragma unroll
    for (int i = 0; i < FIN; i++) t[i] = xr[i];
    float4* a = (float4*)(g_T0 + (size_t)n * S1);
    a[0] = make_float4(t[0], t[1], t[2], t[3]);
    a[1] = make_float4(t[4], t[5], t[6], t[7]);
    a[2] = make_float4(t[8], t[9], 0.f, 0.f);
    a[3] = make_float4(0.f, 0.f, 0.f, 0.f);
    float4 acc[8];
#pragma unroll
    for (int q = 0; q < 8; q++) acc[q] = make_float4(0.f, 0.f, 0.f, 0.f);
#pragma unroll
    for (int i = 0; i < FIN; i++) {
        const float4* wr = (const float4*)(sWp + i * 32);
#pragma unroll
        for (int q = 0; q < 8; q++) {
            float4 wv = wr[q];
            acc[q].x += t[i] * wv.x; acc[q].y += t[i] * wv.y;
            acc[q].z += t[i] * wv.z; acc[q].w += t[i] * wv.w;
        }
    }
    float4* o = (float4*)(g_O1 + (size_t)n * S2);
#pragma unroll
    for (int q = 0; q < 8; q++) o[q] = acc[q];
}

// ---------------- fused props: gather + recursion + node matvec --------------
// Warp-per-node. Edge records loaded coalesced once per 32-edge chunk and
// broadcast via shfl. Gathers are row-aligned scalar loads: prop30 = 1 row =
// 1 line per LDG; prop10 = 2 rows (64B each) per LDG.
// T_new[n] = scale*S*hin[n] - Tprev[n];   O += T_new @ Wk
__global__ void k_prop10f(const float* __restrict__ hin, const float* __restrict__ Tprev,
                          float* __restrict__ hout, const float* __restrict__ Wk,
                          float scale) {
    __shared__ __align__(16) float sW[FIN * 32];
    for (int i = threadIdx.x; i < FIN * 32; i += blockDim.x) {
        int r = i >> 5, c = i & 31;
        sW[i] = (c < HID) ? Wk[r * HID + c] : 0.f;
    }
    __syncthreads();
    int warp = (blockIdx.x * blockDim.x + threadIdx.x) >> 5;
    int lane = threadIdx.x & 31;
    if (warp >= NN) return;
    int n = warp;
    int s = g_rs[n], e = g_rs[n + 1];
    int half = lane >> 4;        // which of the 2 edges this lane serves
    int col  = lane & 15;        // column within the 16-float row
    float acc = 0.f;
    for (int base = s; base < e; base += 32) {
        int idx = base + lane;
        int2 r = (idx < e) ? g_recs[idx] : make_int2(0, 0);   // norm bits 0 -> 0.0f
        int m  = e - base; if (m > 32) m = 32;
        int mm = (m + 1) & ~1;   // round up to even; padded rec contributes 0
#pragma unroll 4
        for (int i = 0; i < mm; i += 2) {
            int ei  = i + half;
            int src = __shfl_sync(0xFFFFFFFF, r.x, ei);
            float c = __int_as_float(__shfl_sync(0xFFFFFFFF, r.y, ei)) * scale;
            acc += c * hin[(size_t)src * S1 + col];
        }
    }
    acc += __shfl_xor_sync(0xFFFFFFFF, acc, 16);   // fold the two edge-halves
    if (Tprev) acc -= Tprev[(size_t)n * S1 + col];
    if (lane < 16) hout[(size_t)n * S1 + lane] = acc;
    // epilogue: O1[n][lane] += sum_i t_i * W[i][lane]
    float o = g_O1[(size_t)n * S2 + lane];
#pragma unroll
    for (int i = 0; i < FIN; i++) {
        float ti = __shfl_sync(0xFFFFFFFF, acc, i);   // lane i holds col i
        o += ti * sW[i * 32 + lane];
    }
    g_O1[(size_t)n * S2 + lane] = o;
}

__global__ void k_prop30f(const float* __restrict__ hin, const float* __restrict__ Tprev,
                          float* __restrict__ hout, const float* __restrict__ Wk,
                          float scale) {
    __shared__ __align__(16) float sW[HID * 32];
    for (int i = threadIdx.x; i < HID * 32; i += blockDim.x) {
        int r = i >> 5, c = i & 31;
        sW[i] = (c < HID) ? Wk[r * HID + c] : 0.f;
    }
    __syncthreads();
    int warp = (blockIdx.x * blockDim.x + threadIdx.x) >> 5;
    int lane = threadIdx.x & 31;
    if (warp >= NN) return;
    int n = warp;
    int s = g_rs[n], e = g_rs[n + 1];
    float acc = 0.f;
    for (int base = s; base < e; base += 32) {
        int idx = base + lane;
        int2 r = (idx < e) ? g_recs[idx] : make_int2(0, 0);
        int m  = e - base; if (m > 32) m = 32;
#pragma unroll 4
        for (int i = 0; i < m; i++) {
            int src = __shfl_sync(0xFFFFFFFF, r.x, i);
            float c = __int_as_float(__shfl_sync(0xFFFFFFFF, r.y, i)) * scale;
            acc += c * hin[(size_t)src * S2 + lane];   // one 128B line per LDG
        }
    }
    if (Tprev) acc -= Tprev[(size_t)n * S2 + lane];
    hout[(size_t)n * S2 + lane] = acc;
    float o = g_O2[(size_t)n * S2 + lane];
#pragma unroll
    for (int i = 0; i < HID; i++) {
        float ti = __shfl_sync(0xFFFFFFFF, acc, i);
        o += ti * sW[i * 32 + lane];
    }
    g_O2[(size_t)n * S2 + lane] = o;
}

// -------- layer-1 final: h=relu(O1+b1); A2=h (pads 0); O2=h@W2[0] ------------
__global__ void k_l1_final(const float* __restrict__ b1, const float* __restrict__ W20) {
    __shared__ __align__(16) float sW0p[HID * 32];
    __shared__ float sb[HID];
    for (int i = threadIdx.x; i < HID * 32; i += blockDim.x) {
        int r = i >> 5, c = i & 31;
        sW0p[i] = (c < HID) ? W20[r * HID + c] : 0.f;
    }
    for (int i = threadIdx.x; i < HID; i += blockDim.x) sb[i] = b1[i];
    __syncthreads();
    int n = blockIdx.x * blockDim.x + threadIdx.x;
    if (n >= NN) return;
    const float* o1 = g_O1 + (size_t)n * S2;
    float h[32];
#pragma unroll
    for (int j = 0; j < HID; j++) h[j] = fmaxf(o1[j] + sb[j], 0.f);
    h[30] = 0.f; h[31] = 0.f;
    float4* a2 = (float4*)(g_A2 + (size_t)n * S2);
#pragma unroll
    for (int q = 0; q < 8; q++)
        a2[q] = make_float4(h[4 * q], h[4 * q + 1], h[4 * q + 2], h[4 * q + 3]);
    float4 acc[8];
#pragma unroll
    for (int q = 0; q < 8; q++) acc[q] = make_float4(0.f, 0.f, 0.f, 0.f);
#pragma unroll
    for (int i = 0; i < HID; i++) {
        const float4* wr = (const float4*)(sW0p + i * 32);
#pragma unroll
        for (int q = 0; q < 8; q++) {
            float4 wv = wr[q];
            acc[q].x += h[i] * wv.x; acc[q].y += h[i] * wv.y;
            acc[q].z += h[i] * wv.z; acc[q].w += h[i] * wv.w;
        }
    }
    float4* o2 = (float4*)(g_O2 + (size_t)n * S2);
#pragma unroll
    for (int q = 0; q < 8; q++) o2[q] = acc[q];
}

// -------- layer-2 final + head: out = relu(O2+b2) @ Wl + bl ------------------
__global__ void k_l2_final(const float* __restrict__ b2,
                           const float* __restrict__ Wl, const float* __restrict__ bl,
                           float* __restrict__ out) {
    __shared__ float sWl[HID * NCLS];
    __shared__ float sb2[HID];
    __shared__ float sbl[NCLS];
    for (int i = threadIdx.x; i < HID * NCLS; i += blockDim.x) sWl[i] = Wl[i];
    for (int i = threadIdx.x; i < HID; i += blockDim.x) sb2[i] = b2[i];
    for (int i = threadIdx.x; i < NCLS; i += blockDim.x) sbl[i] = bl[i];
    __syncthreads();
    int n = blockIdx.x * blockDim.x + threadIdx.x;
    if (n >= NN) return;
    const float* o2 = g_O2 + (size_t)n * S2;
    float h[HID];
#pragma unroll
    for (int j = 0; j < HID; j++) h[j] = fmaxf(o2[j] + sb2[j], 0.f);
    float r[NCLS];
#pragma unroll
    for (int c = 0; c < NCLS; c++) r[c] = sbl[c];
#pragma unroll
    for (int j = 0; j < HID; j++) {
#pragma unroll
        for (int c = 0; c < NCLS; c++) r[c] += h[j] * sWl[j * NCLS + c];
    }
    *(float4*)(out + (size_t)n * NCLS) = make_float4(r[0], r[1], r[2], r[3]);
}

// ---------------- launch -----------------------------------------------------
extern "C" void kernel_launch(void* const* d_in, const int* in_sizes, int n_in,
                              void* d_out, int out_size) {
    const float* x  = (const float*)d_in[0];
    const int*   ei = (const int*)d_in[1];
    const float* ew = (const float*)d_in[2];
    const float* W1 = (const float*)d_in[3];
    const float* b1 = (const float*)d_in[4];
    const float* W2 = (const float*)d_in[5];
    const float* b2 = (const float*)d_in[6];
    const float* Wl = (const float*)d_in[7];
    const float* bl = (const float*)d_in[8];
    float* out = (float*)d_out;

    const int* src = ei;
    const int* dst = ei + NE;

    float *T0, *T1, *T2, *A2, *B2, *C2;
    cudaGetSymbolAddress((void**)&T0, g_T0);
    cudaGetSymbolAddress((void**)&T1, g_T1);
    cudaGetSymbolAddress((void**)&T2, g_T2);
    cudaGetSymbolAddress((void**)&A2, g_A2);
    cudaGetSymbolAddress((void**)&B2, g_B2);
    cudaGetSymbolAddress((void**)&C2, g_C2);

    dim3 blk(256);
    dim3 ng((NN + 255) / 256);
    dim3 eg((NE + 255) / 256);
    dim3 nw((NN * 32 + 255) / 256);   // warp-per-node prop grids

    // CSR build
    k_zero<<<ng, blk>>>();
    k_deg<<<eg, blk>>>(src, dst, ew);
    k_scan1<<<SCAN_NB, SCAN_BS>>>();
    k_scan2<<<1, 256>>>();
    k_scan3<<<ng, blk>>>();
    k_normbuild<<<eg, blk>>>(src, dst, ew);

    // ---- layer 1 (dim 10, fp32 rows of 16) ----
    k_l1_init<<<ng, blk>>>(x, W1 + 0 * FIN * HID);
    k_prop10f<<<nw, blk>>>(T0, nullptr, T1, W1 + 1 * FIN * HID, 1.0f);  // T1
    k_prop10f<<<nw, blk>>>(T1, T0, T2, W1 + 2 * FIN * HID, 2.0f);       // T2
    k_prop10f<<<nw, blk>>>(T2, T1, T0, W1 + 3 * FIN * HID, 2.0f);       // T3
    k_prop10f<<<nw, blk>>>(T0, T2, T1, W1 + 4 * FIN * HID, 2.0f);       // T4
    k_l1_final<<<ng, blk>>>(b1, W2 + 0 * HID * HID);

    // ---- layer 2 (dim 30, fp32 rows of 32) ----
    k_prop30f<<<nw, blk>>>(A2, nullptr, B2, W2 + 1 * HID * HID, 1.0f);  // T1
    k_prop30f<<<nw, blk>>>(B2, A2, C2, W2 + 2 * HID * HID, 2.0f);       // T2
    k_prop30f<<<nw, blk>>>(C2, B2, A2, W2 + 3 * HID * HID, 2.0f);       // T3
    k_prop30f<<<nw, blk>>>(A2, C2, B2, W2 + 4 * HID * HID, 2.0f);       // T4
    k_l2_final<<<ng, blk>>>(b2, Wl, bl, out);
}

// round 12
// speedup vs baseline: 1.3590x; 1.3590x over previous
#include <cuda_runtime.h>
#include <cstddef>

#define NN   100000
#define NE   3200000
#define FIN  10
#define HID  30
#define NCLS 4
#define S1   16   // layer-1 fp32 T row stride (64B, line-aligned)
#define S2   32   // layer-2 / accumulator fp32 row stride (128B = 1 line)

#define SCAN_BS 512
#define SCAN_NB ((NN + SCAN_BS - 1) / SCAN_BS)   // 196

// ---------------- scratch (static device globals; zero-initialized) ---------
__device__ __align__(16) float g_deg[NN];
__device__ __align__(16) int   g_cnt[NN];
__device__ __align__(16) int   g_rs[NN + 1];
__device__ __align__(16) int   g_cur[NN];
__device__ __align__(16) int   g_bsum[SCAN_NB];
__device__ __align__(16) int   g_boff[SCAN_NB];
__device__ __align__(16) int2  g_recs[NE];       // {src, norm bits} sorted by dst
__device__ __align__(16) float g_T0[NN * S1];
__device__ __align__(16) float g_T1[NN * S1];
__device__ __align__(16) float g_T2[NN * S1];
__device__ __align__(16) float g_A2[NN * S2];
__device__ __align__(16) float g_B2[NN * S2];
__device__ __align__(16) float g_C2[NN * S2];
__device__ __align__(16) float g_O1[NN * S2];
__device__ __align__(16) float g_O2[NN * S2];

// ---------------- degree + histogram (cnt pre-zeroed by prior scan1) ---------
__global__ void k_deg(const int* __restrict__ src, const int* __restrict__ dst,
                      const float* __restrict__ w) {
    int e = blockIdx.x * blockDim.x + threadIdx.x;
    if (e >= NE) return;
    int s = src[e], d = dst[e];
    if (s != d) atomicAdd(&g_deg[s], w[e]);
    atomicAdd(&g_cnt[d], 1);
}

// ---------------- CSR build: 2-level exclusive scan --------------------------
__global__ void k_scan1() {
    __shared__ int sh[SCAN_BS];
    int tid = threadIdx.x;
    int i = blockIdx.x * SCAN_BS + tid;
    int v = (i < NN) ? g_cnt[i] : 0;
    sh[tid] = v;
    __syncthreads();
#pragma unroll
    for (int ofs = 1; ofs < SCAN_BS; ofs <<= 1) {
        int t = (tid >= ofs) ? sh[tid - ofs] : 0;
        __syncthreads();
        sh[tid] += t;
        __syncthreads();
    }
    if (i < NN) {
        g_rs[i] = sh[tid] - v;   // exclusive
        g_cnt[i] = 0;            // reset for next replay
    }
    if (tid == SCAN_BS - 1) g_bsum[blockIdx.x] = sh[tid];
}

__global__ void k_scan2() {
    __shared__ int sh[256];
    int tid = threadIdx.x;
    int v = (tid < SCAN_NB) ? g_bsum[tid] : 0;
    sh[tid] = v;
    __syncthreads();
#pragma unroll
    for (int ofs = 1; ofs < 256; ofs <<= 1) {
        int t = (tid >= ofs) ? sh[tid - ofs] : 0;
        __syncthreads();
        sh[tid] += t;
        __syncthreads();
    }
    if (tid < SCAN_NB) g_boff[tid] = sh[tid] - v;
}

__global__ void k_scan3() {
    int i = blockIdx.x * blockDim.x + threadIdx.x;
    if (i < NN) {
        int r = g_rs[i] + g_boff[i / SCAN_BS];
        g_rs[i] = r;
        g_cur[i] = r;
    }
    if (i == 0) g_rs[NN] = NE;
}

// ---------------- fused norm + record scatter --------------------------------
__global__ void k_normbuild(const int* __restrict__ src, const int* __restrict__ dst,
                            const float* __restrict__ w) {
    int e = blockIdx.x * blockDim.x + threadIdx.x;
    if (e >= NE) return;
    int s = src[e], d = dst[e];
    float we = (s == d) ? 0.f : w[e];
    float ds = g_deg[s], dd = g_deg[d];
    float is = (ds > 0.f) ? rsqrtf(ds) : 0.f;
    float id = (dd > 0.f) ? rsqrtf(dd) : 0.f;
    float norm = -is * we * id;
    int p = atomicAdd(&g_cur[d], 1);
    g_recs[p] = make_int2(s, __float_as_int(norm));
}

// ---------------- layer 1 init: T0 = pad16(x), O1 = x @ W1[0]; zero deg ------
__global__ void k_l1_init(const float* __restrict__ x, const float* __restrict__ W0) {
    __shared__ __align__(16) float sWp[FIN * 32];
    for (int i = threadIdx.x; i < FIN * 32; i += blockDim.x) {
        int r = i >> 5, c = i & 31;
        sWp[i] = (c < HID) ? W0[r * HID + c] : 0.f;
    }
    __syncthreads();
    int n = blockIdx.x * blockDim.x + threadIdx.x;
    if (n >= NN) return;
    g_deg[n] = 0.f;              // reset for next replay (normbuild already consumed it)
    float t[FIN];
    const float* xr = x + (size_t)n * FIN;
#pragma unroll
    for (int i = 0; i < FIN; i++) t[i] = xr[i];
    float4* a = (float4*)(g_T0 + (size_t)n * S1);
    a[0] = make_float4(t[0], t[1], t[2], t[3]);
    a[1] = make_float4(t[4], t[5], t[6], t[7]);
    a[2] = make_float4(t[8], t[9], 0.f, 0.f);
    a[3] = make_float4(0.f, 0.f, 0.f, 0.f);
    float4 acc[8];
#pragma unroll
    for (int q = 0; q < 8; q++) acc[q] = make_float4(0.f, 0.f, 0.f, 0.f);
#pragma unroll
    for (int i = 0; i < FIN; i++) {
        const float4* wr = (const float4*)(sWp + i * 32);
#pragma unroll
        for (int q = 0; q < 8; q++) {
            float4 wv = wr[q];
            acc[q].x += t[i] * wv.x; acc[q].y += t[i] * wv.y;
            acc[q].z += t[i] * wv.z; acc[q].w += t[i] * wv.w;
        }
    }
    float4* o = (float4*)(g_O1 + (size_t)n * S2);
#pragma unroll
    for (int q = 0; q < 8; q++) o[q] = acc[q];
}

// ---------------- warp-per-node props with fused node matvec -----------------
// T_new[n] = scale*S*hin[n] - Tprev[n];  optional store;  O += T_new @ Wk
// prop10: 8 edge-subgroups x 4 lanes (float4 slot = lane&3, 16-float rows).
__global__ void k_prop10(const float* __restrict__ hin, const float* __restrict__ Tprev,
                         float* __restrict__ hout, const float* __restrict__ Wk,
                         float scale) {
    __shared__ __align__(16) float sW[FIN * 32];
    for (int i = threadIdx.x; i < FIN * 32; i += blockDim.x) {
        int r = i >> 5, c = i & 31;
        sW[i] = (c < HID) ? Wk[r * HID + c] : 0.f;
    }
    __syncthreads();
    int warp = (blockIdx.x * blockDim.x + threadIdx.x) >> 5;
    int lane = threadIdx.x & 31;
    if (warp >= NN) return;
    int n = warp;
    int off = lane & 3;          // float4 slot
    int sub = lane >> 2;         // 0..7 edge subgroup
    int s = g_rs[n], e = g_rs[n + 1];
    float4 acc = make_float4(0.f, 0.f, 0.f, 0.f);
    int i = s + sub;
    for (; i + 8 < e; i += 16) {
        int2 r0 = g_recs[i], r1 = g_recs[i + 8];
        float c0 = __int_as_float(r0.y) * scale;
        float c1 = __int_as_float(r1.y) * scale;
        float4 v0 = *(const float4*)(hin + ((size_t)r0.x << 4) + (off << 2));
        float4 v1 = *(const float4*)(hin + ((size_t)r1.x << 4) + (off << 2));
        acc.x += c0 * v0.x + c1 * v1.x;
        acc.y += c0 * v0.y + c1 * v1.y;
        acc.z += c0 * v0.z + c1 * v1.z;
        acc.w += c0 * v0.w + c1 * v1.w;
    }
    if (i < e) {
        int2 r = g_recs[i];
        float c = __int_as_float(r.y) * scale;
        float4 v = *(const float4*)(hin + ((size_t)r.x << 4) + (off << 2));
        acc.x += c * v.x; acc.y += c * v.y; acc.z += c * v.z; acc.w += c * v.w;
    }
#pragma unroll
    for (int m = 4; m <= 16; m <<= 1) {
        acc.x += __shfl_xor_sync(0xFFFFFFFF, acc.x, m);
        acc.y += __shfl_xor_sync(0xFFFFFFFF, acc.y, m);
        acc.z += __shfl_xor_sync(0xFFFFFFFF, acc.z, m);
        acc.w += __shfl_xor_sync(0xFFFFFFFF, acc.w, m);
    }
    // apply recursion on slot-owner lanes (0..3) BEFORE broadcasting
    if (lane < 4 && Tprev) {
        float4 v = *(const float4*)(Tprev + ((size_t)n << 4) + (lane << 2));
        acc.x -= v.x; acc.y -= v.y; acc.z -= v.z; acc.w -= v.w;
    }
    if (lane < 4 && hout)
        *(float4*)(hout + ((size_t)n << 4) + (lane << 2)) = acc;
    // epilogue: O1[n][lane] += sum_j t_j * W[j][lane]; t_j on lane j>>2, comp j&3
    float comp[4] = {acc.x, acc.y, acc.z, acc.w};
    float o = g_O1[(size_t)n * S2 + lane];
#pragma unroll
    for (int j = 0; j < FIN; j++) {
        float tj = __shfl_sync(0xFFFFFFFF, comp[j & 3], j >> 2);
        o += tj * sW[j * 32 + lane];
    }
    g_O1[(size_t)n * S2 + lane] = o;
}

// prop30: 4 edge-subgroups x 8 lanes (float4 slot = lane&7, 32-float rows).
__global__ void k_prop30(const float* __restrict__ hin, const float* __restrict__ Tprev,
                         float* __restrict__ hout, const float* __restrict__ Wk,
                         float scale) {
    __shared__ __align__(16) float sW[HID * 32];
    for (int i = threadIdx.x; i < HID * 32; i += blockDim.x) {
        int r = i >> 5, c = i & 31;
        sW[i] = (c < HID) ? Wk[r * HID + c] : 0.f;
    }
    __syncthreads();
    int warp = (blockIdx.x * blockDim.x + threadIdx.x) >> 5;
    int lane = threadIdx.x & 31;
    if (warp >= NN) return;
    int n = warp;
    int off = lane & 7;
    int sub = lane >> 3;         // 0..3
    int s = g_rs[n], e = g_rs[n + 1];
    float4 acc = make_float4(0.f, 0.f, 0.f, 0.f);
    int i = s + sub;
    for (; i + 4 < e; i += 8) {
        int2 r0 = g_recs[i], r1 = g_recs[i + 4];
        float c0 = __int_as_float(r0.y) * scale;
        float c1 = __int_as_float(r1.y) * scale;
        float4 v0 = *(const float4*)(hin + ((size_t)r0.x << 5) + (off << 2));
        float4 v1 = *(const float4*)(hin + ((size_t)r1.x << 5) + (off << 2));
        acc.x += c0 * v0.x + c1 * v1.x;
        acc.y += c0 * v0.y + c1 * v1.y;
        acc.z += c0 * v0.z + c1 * v1.z;
        acc.w += c0 * v0.w + c1 * v1.w;
    }
    if (i < e) {
        int2 r = g_recs[i];
        float c = __int_as_float(r.y) * scale;
        float4 v = *(const float4*)(hin + ((size_t)r.x << 5) + (off << 2));
        acc.x += c * v.x; acc.y += c * v.y; acc.z += c * v.z; acc.w += c * v.w;
    }
#pragma unroll
    for (int m = 8; m <= 16; m <<= 1) {
        acc.x += __shfl_xor_sync(0xFFFFFFFF, acc.x, m);
        acc.y += __shfl_xor_sync(0xFFFFFFFF, acc.y, m);
        acc.z += __shfl_xor_sync(0xFFFFFFFF, acc.z, m);
        acc.w += __shfl_xor_sync(0xFFFFFFFF, acc.w, m);
    }
    if (lane < 8 && Tprev) {
        float4 v = *(const float4*)(Tprev + ((size_t)n << 5) + (lane << 2));
        acc.x -= v.x; acc.y -= v.y; acc.z -= v.z; acc.w -= v.w;
    }
    if (lane < 8 && hout)
        *(float4*)(hout + ((size_t)n << 5) + (lane << 2)) = acc;
    float comp[4] = {acc.x, acc.y, acc.z, acc.w};
    float o = g_O2[(size_t)n * S2 + lane];
#pragma unroll
    for (int j = 0; j < HID; j++) {
        float tj = __shfl_sync(0xFFFFFFFF, comp[j & 3], j >> 2);
        o += tj * sW[j * 32 + lane];
    }
    g_O2[(size_t)n * S2 + lane] = o;
}

// -------- layer-1 final: h=relu(O1+b1); A2=h (pads 0); O2=h@W2[0] ------------
__global__ void k_l1_final(const float* __restrict__ b1, const float* __restrict__ W20) {
    __shared__ __align__(16) float sW0p[HID * 32];
    __shared__ float sb[HID];
    for (int i = threadIdx.x; i < HID * 32; i += blockDim.x) {
        int r = i >> 5, c = i & 31;
        sW0p[i] = (c < HID) ? W20[r * HID + c] : 0.f;
    }
    for (int i = threadIdx.x; i < HID; i += blockDim.x) sb[i] = b1[i];
    __syncthreads();
    int n = blockIdx.x * blockDim.x + threadIdx.x;
    if (n >= NN) return;
    const float* o1 = g_O1 + (size_t)n * S2;
    float h[32];
#pragma unroll
    for (int j = 0; j < HID; j++) h[j] = fmaxf(o1[j] + sb[j], 0.f);
    h[30] = 0.f; h[31] = 0.f;
    float4* a2 = (float4*)(g_A2 + (size_t)n * S2);
#pragma unroll
    for (int q = 0; q < 8; q++)
        a2[q] = make_float4(h[4 * q], h[4 * q + 1], h[4 * q + 2], h[4 * q + 3]);
    float4 acc[8];
#pragma unroll
    for (int q = 0; q < 8; q++) acc[q] = make_float4(0.f, 0.f, 0.f, 0.f);
#pragma unroll
    for (int i = 0; i < HID; i++) {
        const float4* wr = (const float4*)(sW0p + i * 32);
#pragma unroll
        for (int q = 0; q < 8; q++) {
            float4 wv = wr[q];
            acc[q].x += h[i] * wv.x; acc[q].y += h[i] * wv.y;
            acc[q].z += h[i] * wv.z; acc[q].w += h[i] * wv.w;
        }
    }
    float4* o2 = (float4*)(g_O2 + (size_t)n * S2);
#pragma unroll
    for (int q = 0; q < 8; q++) o2[q] = acc[q];
}

// -------- layer-2 final + head: out = relu(O2+b2) @ Wl + bl ------------------
__global__ void k_l2_final(const float* __restrict__ b2,
                           const float* __restrict__ Wl, const float* __restrict__ bl,
                           float* __restrict__ out) {
    __shared__ float sWl[HID * NCLS];
    __shared__ float sb2[HID];
    __shared__ float sbl[NCLS];
    for (int i = threadIdx.x; i < HID * NCLS; i += blockDim.x) sWl[i] = Wl[i];
    for (int i = threadIdx.x; i < HID; i += blockDim.x) sb2[i] = b2[i];
    for (int i = threadIdx.x; i < NCLS; i += blockDim.x) sbl[i] = bl[i];
    __syncthreads();
    int n = blockIdx.x * blockDim.x + threadIdx.x;
    if (n >= NN) return;
    const float* o2 = g_O2 + (size_t)n * S2;
    float h[HID];
#pragma unroll
    for (int j = 0; j < HID; j++) h[j] = fmaxf(o2[j] + sb2[j], 0.f);
    float r[NCLS];
#pragma unroll
    for (int c = 0; c < NCLS; c++) r[c] = sbl[c];
#pragma unroll
    for (int j = 0; j < HID; j++) {
#pragma unroll
        for (int c = 0; c < NCLS; c++) r[c] += h[j] * sWl[j * NCLS + c];
    }
    *(float4*)(out + (size_t)n * NCLS) = make_float4(r[0], r[1], r[2], r[3]);
}

// ---------------- launch -----------------------------------------------------
extern "C" void kernel_launch(void* const* d_in, const int* in_sizes, int n_in,
                              void* d_out, int out_size) {
    const float* x  = (const float*)d_in[0];
    const int*   ei = (const int*)d_in[1];
    const float* ew = (const float*)d_in[2];
    const float* W1 = (const float*)d_in[3];
    const float* b1 = (const float*)d_in[4];
    const float* W2 = (const float*)d_in[5];
    const float* b2 = (const float*)d_in[6];
    const float* Wl = (const float*)d_in[7];
    const float* bl = (const float*)d_in[8];
    float* out = (float*)d_out;

    const int* src = ei;
    const int* dst = ei + NE;

    float *T0, *T1, *T2, *A2, *B2, *C2;
    cudaGetSymbolAddress((void**)&T0, g_T0);
    cudaGetSymbolAddress((void**)&T1, g_T1);
    cudaGetSymbolAddress((void**)&T2, g_T2);
    cudaGetSymbolAddress((void**)&A2, g_A2);
    cudaGetSymbolAddress((void**)&B2, g_B2);
    cudaGetSymbolAddress((void**)&C2, g_C2);

    dim3 blk(256);
    dim3 ng((NN + 255) / 256);
    dim3 eg((NE + 255) / 256);
    dim3 nw((NN * 32 + 255) / 256);   // warp-per-node prop grids

    // CSR build (cnt/deg pre-zeroed by previous replay / static init)
    k_deg<<<eg, blk>>>(src, dst, ew);
    k_scan1<<<SCAN_NB, SCAN_BS>>>();
    k_scan2<<<1, 256>>>();
    k_scan3<<<ng, blk>>>();
    k_normbuild<<<eg, blk>>>(src, dst, ew);

    // ---- layer 1 (dim 10, fp32 rows of 16) ----
    k_l1_init<<<ng, blk>>>(x, W1 + 0 * FIN * HID);
    k_prop10<<<nw, blk>>>(T0, nullptr, T1, W1 + 1 * FIN * HID, 1.0f);   // T1; O1+=T1@W1
    k_prop10<<<nw, blk>>>(T1, T0, T2, W1 + 2 * FIN * HID, 2.0f);        // T2; O1+=T2@W2
    k_prop10<<<nw, blk>>>(T2, T1, T0, W1 + 3 * FIN * HID, 2.0f);        // T3; O1+=T3@W3
    k_prop10<<<nw, blk>>>(T0, T2, nullptr, W1 + 4 * FIN * HID, 2.0f);   // T4; O1+=T4@W4
    k_l1_final<<<ng, blk>>>(b1, W2 + 0 * HID * HID);

    // ---- layer 2 (dim 30, fp32 rows of 32) ----
    k_prop30<<<nw, blk>>>(A2, nullptr, B2, W2 + 1 * HID * HID, 1.0f);   // T1
    k_prop30<<<nw, blk>>>(B2, A2, C2, W2 + 2 * HID * HID, 2.0f);        // T2
    k_prop30<<<nw, blk>>>(C2, B2, A2, W2 + 3 * HID * HID, 2.0f);        // T3
    k_prop30<<<nw, blk>>>(A2, C2, nullptr, W2 + 4 * HID * HID, 2.0f);   // T4
    k_l2_final<<<ng, blk>>>(b2, Wl, bl, out);
}

// round 13
// speedup vs baseline: 1.4642x; 1.0774x over previous
#include <cuda_runtime.h>
#include <cstddef>

#define NN   100000
#define NE   3200000
#define FIN  10
#define HID  30
#define NCLS 4
#define S1   16   // layer-1 fp32 T row stride (64B, line-aligned)
#define S2   32   // layer-2 / accumulator fp32 row stride (128B = 1 line)

#define SCAN_BS 512
#define SCAN_NB ((NN + SCAN_BS - 1) / SCAN_BS)   // 196

// ---------------- scratch (static device globals; zero-initialized) ---------
__device__ __align__(16) float g_deg[NN];
__device__ __align__(16) int   g_cnt[NN];
__device__ __align__(16) int   g_rs[NN + 1];
__device__ __align__(16) int   g_cur[NN];
__device__ __align__(16) int   g_bsum[SCAN_NB];
__device__ __align__(16) int   g_boff[SCAN_NB];
__device__ __align__(16) int2  g_recs[NE];       // {src, norm bits} sorted by dst
__device__ __align__(16) float g_T0[NN * S1];
__device__ __align__(16) float g_T1[NN * S1];
__device__ __align__(16) float g_T2[NN * S1];
__device__ __align__(16) float g_A2[NN * S2];
__device__ __align__(16) float g_B2[NN * S2];
__device__ __align__(16) float g_C2[NN * S2];
__device__ __align__(16) float g_O1[NN * S2];
__device__ __align__(16) float g_O2[NN * S2];

// ---------------- degree + histogram (cnt pre-zeroed by prior scan1) ---------
__global__ void k_deg(const int* __restrict__ src, const int* __restrict__ dst,
                      const float* __restrict__ w) {
    int e = blockIdx.x * blockDim.x + threadIdx.x;
    if (e >= NE) return;
    int s = src[e], d = dst[e];
    if (s != d) atomicAdd(&g_deg[s], w[e]);
    atomicAdd(&g_cnt[d], 1);
}

// ---------------- CSR build: 2-level exclusive scan --------------------------
__global__ void k_scan1() {
    __shared__ int sh[SCAN_BS];
    int tid = threadIdx.x;
    int i = blockIdx.x * SCAN_BS + tid;
    int v = (i < NN) ? g_cnt[i] : 0;
    sh[tid] = v;
    __syncthreads();
#pragma unroll
    for (int ofs = 1; ofs < SCAN_BS; ofs <<= 1) {
        int t = (tid >= ofs) ? sh[tid - ofs] : 0;
        __syncthreads();
        sh[tid] += t;
        __syncthreads();
    }
    if (i < NN) {
        g_rs[i] = sh[tid] - v;   // exclusive
        g_cnt[i] = 0;            // reset for next replay
    }
    if (tid == SCAN_BS - 1) g_bsum[blockIdx.x] = sh[tid];
}

__global__ void k_scan2() {
    __shared__ int sh[256];
    int tid = threadIdx.x;
    int v = (tid < SCAN_NB) ? g_bsum[tid] : 0;
    sh[tid] = v;
    __syncthreads();
#pragma unroll
    for (int ofs = 1; ofs < 256; ofs <<= 1) {
        int t = (tid >= ofs) ? sh[tid - ofs] : 0;
        __syncthreads();
        sh[tid] += t;
        __syncthreads();
    }
    if (tid < SCAN_NB) g_boff[tid] = sh[tid] - v;
}

__global__ void k_scan3() {
    int i = blockIdx.x * blockDim.x + threadIdx.x;
    if (i < NN) {
        int r = g_rs[i] + g_boff[i / SCAN_BS];
        g_rs[i] = r;
        g_cur[i] = r;
    }
    if (i == 0) g_rs[NN] = NE;
}

// ---------------- fused norm + record scatter --------------------------------
__global__ void k_normbuild(const int* __restrict__ src, const int* __restrict__ dst,
                            const float* __restrict__ w) {
    int e = blockIdx.x * blockDim.x + threadIdx.x;
    if (e >= NE) return;
    int s = src[e], d = dst[e];
    float we = (s == d) ? 0.f : w[e];
    float ds = g_deg[s], dd = g_deg[d];
    float is = (ds > 0.f) ? rsqrtf(ds) : 0.f;
    float id = (dd > 0.f) ? rsqrtf(dd) : 0.f;
    float norm = -is * we * id;
    int p = atomicAdd(&g_cur[d], 1);
    g_recs[p] = make_int2(s, __float_as_int(norm));
}

// ---------------- layer 1 init: T0 = pad16(x), O1 = x @ W1[0]; zero deg ------
__global__ void k_l1_init(const float* __restrict__ x, const float* __restrict__ W0) {
    __shared__ __align__(16) float sWp[FIN * 32];
    for (int i = threadIdx.x; i < FIN * 32; i += blockDim.x) {
        int r = i >> 5, c = i & 31;
        sWp[i] = (c < HID) ? W0[r * HID + c] : 0.f;
    }
    __syncthreads();
    int n = blockIdx.x * blockDim.x + threadIdx.x;
    if (n >= NN) return;
    g_deg[n] = 0.f;              // reset for next replay (normbuild already consumed it)
    float t[FIN];
    const float* xr = x + (size_t)n * FIN;
#pragma unroll
    for (int i = 0; i < FIN; i++) t[i] = xr[i];
    float4* a = (float4*)(g_T0 + (size_t)n * S1);
    a[0] = make_float4(t[0], t[1], t[2], t[3]);
    a[1] = make_float4(t[4], t[5], t[6], t[7]);
    a[2] = make_float4(t[8], t[9], 0.f, 0.f);
    a[3] = make_float4(0.f, 0.f, 0.f, 0.f);
    float4 acc[8];
#pragma unroll
    for (int q = 0; q < 8; q++) acc[q] = make_float4(0.f, 0.f, 0.f, 0.f);
#pragma unroll
    for (int i = 0; i < FIN; i++) {
        const float4* wr = (const float4*)(sWp + i * 32);
#pragma unroll
        for (int q = 0; q < 8; q++) {
            float4 wv = wr[q];
            acc[q].x += t[i] * wv.x; acc[q].y += t[i] * wv.y;
            acc[q].z += t[i] * wv.z; acc[q].w += t[i] * wv.w;
        }
    }
    float4* o = (float4*)(g_O1 + (size_t)n * S2);
#pragma unroll
    for (int q = 0; q < 8; q++) o[q] = acc[q];
}

// ---------------- warp-per-node props, fused matvec epilogue -----------------
// Gather loop identical to R8 (known-good). Epilogue reads weights directly
// via __ldg (L1-resident), no smem staging, no syncthreads.

// prop10: 8 edge-subgroups x 4 lanes (float4 slot = lane&3, 16-float rows).
__global__ void k_prop10(const float* __restrict__ hin, const float* __restrict__ Tprev,
                         float* __restrict__ hout, const float* __restrict__ Wk,
                         float scale) {
    int warp = (blockIdx.x * blockDim.x + threadIdx.x) >> 5;
    int lane = threadIdx.x & 31;
    if (warp >= NN) return;
    int n = warp;
    int off = lane & 3;
    int sub = lane >> 2;
    int s = g_rs[n], e = g_rs[n + 1];
    float4 acc = make_float4(0.f, 0.f, 0.f, 0.f);
    int i = s + sub;
    for (; i + 8 < e; i += 16) {
        int2 r0 = g_recs[i], r1 = g_recs[i + 8];
        float c0 = __int_as_float(r0.y) * scale;
        float c1 = __int_as_float(r1.y) * scale;
        float4 v0 = *(const float4*)(hin + ((size_t)r0.x << 4) + (off << 2));
        float4 v1 = *(const float4*)(hin + ((size_t)r1.x << 4) + (off << 2));
        acc.x += c0 * v0.x + c1 * v1.x;
        acc.y += c0 * v0.y + c1 * v1.y;
        acc.z += c0 * v0.z + c1 * v1.z;
        acc.w += c0 * v0.w + c1 * v1.w;
    }
    if (i < e) {
        int2 r = g_recs[i];
        float c = __int_as_float(r.y) * scale;
        float4 v = *(const float4*)(hin + ((size_t)r.x << 4) + (off << 2));
        acc.x += c * v.x; acc.y += c * v.y; acc.z += c * v.z; acc.w += c * v.w;
    }
#pragma unroll
    for (int m = 4; m <= 16; m <<= 1) {
        acc.x += __shfl_xor_sync(0xFFFFFFFF, acc.x, m);
        acc.y += __shfl_xor_sync(0xFFFFFFFF, acc.y, m);
        acc.z += __shfl_xor_sync(0xFFFFFFFF, acc.z, m);
        acc.w += __shfl_xor_sync(0xFFFFFFFF, acc.w, m);
    }
    if (lane < 4 && Tprev) {
        float4 v = *(const float4*)(Tprev + ((size_t)n << 4) + (lane << 2));
        acc.x -= v.x; acc.y -= v.y; acc.z -= v.z; acc.w -= v.w;
    }
    if (lane < 4)
        *(float4*)(hout + ((size_t)n << 4) + (lane << 2)) = acc;
    // epilogue: O1[n][lane] += sum_j t_j * Wk[j][lane]
    float comp[4] = {acc.x, acc.y, acc.z, acc.w};
    float o = g_O1[(size_t)n * S2 + lane];
#pragma unroll
    for (int j = 0; j < FIN; j++) {
        float tj = __shfl_sync(0xFFFFFFFF, comp[j & 3], j >> 2);
        float wv = (lane < HID) ? __ldg(Wk + j * HID + lane) : 0.f;
        o += tj * wv;
    }
    g_O1[(size_t)n * S2 + lane] = o;
}

// prop10_last: no T store; O1 finalized in-register -> h=relu(O1+b1);
// A2 = h (pads 0); O2 = h @ W20.
__global__ void k_prop10_last(const float* __restrict__ hin, const float* __restrict__ Tprev,
                              const float* __restrict__ Wk, const float* __restrict__ b1,
                              const float* __restrict__ W20, float scale) {
    int warp = (blockIdx.x * blockDim.x + threadIdx.x) >> 5;
    int lane = threadIdx.x & 31;
    if (warp >= NN) return;
    int n = warp;
    int off = lane & 3;
    int sub = lane >> 2;
    int s = g_rs[n], e = g_rs[n + 1];
    float4 acc = make_float4(0.f, 0.f, 0.f, 0.f);
    int i = s + sub;
    for (; i + 8 < e; i += 16) {
        int2 r0 = g_recs[i], r1 = g_recs[i + 8];
        float c0 = __int_as_float(r0.y) * scale;
        float c1 = __int_as_float(r1.y) * scale;
        float4 v0 = *(const float4*)(hin + ((size_t)r0.x << 4) + (off << 2));
        float4 v1 = *(const float4*)(hin + ((size_t)r1.x << 4) + (off << 2));
        acc.x += c0 * v0.x + c1 * v1.x;
        acc.y += c0 * v0.y + c1 * v1.y;
        acc.z += c0 * v0.z + c1 * v1.z;
        acc.w += c0 * v0.w + c1 * v1.w;
    }
    if (i < e) {
        int2 r = g_recs[i];
        float c = __int_as_float(r.y) * scale;
        float4 v = *(const float4*)(hin + ((size_t)r.x << 4) + (off << 2));
        acc.x += c * v.x; acc.y += c * v.y; acc.z += c * v.z; acc.w += c * v.w;
    }
#pragma unroll
    for (int m = 4; m <= 16; m <<= 1) {
        acc.x += __shfl_xor_sync(0xFFFFFFFF, acc.x, m);
        acc.y += __shfl_xor_sync(0xFFFFFFFF, acc.y, m);
        acc.z += __shfl_xor_sync(0xFFFFFFFF, acc.z, m);
        acc.w += __shfl_xor_sync(0xFFFFFFFF, acc.w, m);
    }
    if (lane < 4) {
        float4 v = *(const float4*)(Tprev + ((size_t)n << 4) + (lane << 2));
        acc.x -= v.x; acc.y -= v.y; acc.z -= v.z; acc.w -= v.w;
    }
    float comp[4] = {acc.x, acc.y, acc.z, acc.w};
    float o = g_O1[(size_t)n * S2 + lane];
#pragma unroll
    for (int j = 0; j < FIN; j++) {
        float tj = __shfl_sync(0xFFFFFFFF, comp[j & 3], j >> 2);
        float wv = (lane < HID) ? __ldg(Wk + j * HID + lane) : 0.f;
        o += tj * wv;
    }
    // h = relu(o + b1)
    float h = 0.f;
    if (lane < HID) h = fmaxf(o + __ldg(b1 + lane), 0.f);
    g_A2[(size_t)n * S2 + lane] = h;      // pads (30,31) get 0
    // O2 = h @ W20
    float o2 = 0.f;
#pragma unroll
    for (int j = 0; j < HID; j++) {
        float hj = __shfl_sync(0xFFFFFFFF, h, j);
        float wv = (lane < HID) ? __ldg(W20 + j * HID + lane) : 0.f;
        o2 += hj * wv;
    }
    g_O2[(size_t)n * S2 + lane] = o2;
}

// prop30: 4 edge-subgroups x 8 lanes (float4 slot = lane&7, 32-float rows).
__global__ void k_prop30(const float* __restrict__ hin, const float* __restrict__ Tprev,
                         float* __restrict__ hout, const float* __restrict__ Wk,
                         float scale) {
    int warp = (blockIdx.x * blockDim.x + threadIdx.x) >> 5;
    int lane = threadIdx.x & 31;
    if (warp >= NN) return;
    int n = warp;
    int off = lane & 7;
    int sub = lane >> 3;
    int s = g_rs[n], e = g_rs[n + 1];
    float4 acc = make_float4(0.f, 0.f, 0.f, 0.f);
    int i = s + sub;
    for (; i + 4 < e; i += 8) {
        int2 r0 = g_recs[i], r1 = g_recs[i + 4];
        float c0 = __int_as_float(r0.y) * scale;
        float c1 = __int_as_float(r1.y) * scale;
        float4 v0 = *(const float4*)(hin + ((size_t)r0.x << 5) + (off << 2));
        float4 v1 = *(const float4*)(hin + ((size_t)r1.x << 5) + (off << 2));
        acc.x += c0 * v0.x + c1 * v1.x;
        acc.y += c0 * v0.y + c1 * v1.y;
        acc.z += c0 * v0.z + c1 * v1.z;
        acc.w += c0 * v0.w + c1 * v1.w;
    }
    if (i < e) {
        int2 r = g_recs[i];
        float c = __int_as_float(r.y) * scale;
        float4 v = *(const float4*)(hin + ((size_t)r.x << 5) + (off << 2));
        acc.x += c * v.x; acc.y += c * v.y; acc.z += c * v.z; acc.w += c * v.w;
    }
#pragma unroll
    for (int m = 8; m <= 16; m <<= 1) {
        acc.x += __shfl_xor_sync(0xFFFFFFFF, acc.x, m);
        acc.y += __shfl_xor_sync(0xFFFFFFFF, acc.y, m);
        acc.z += __shfl_xor_sync(0xFFFFFFFF, acc.z, m);
        acc.w += __shfl_xor_sync(0xFFFFFFFF, acc.w, m);
    }
    if (lane < 8 && Tprev) {
        float4 v = *(const float4*)(Tprev + ((size_t)n << 5) + (lane << 2));
        acc.x -= v.x; acc.y -= v.y; acc.z -= v.z; acc.w -= v.w;
    }
    if (lane < 8)
        *(float4*)(hout + ((size_t)n << 5) + (lane << 2)) = acc;
    float comp[4] = {acc.x, acc.y, acc.z, acc.w};
    float o = g_O2[(size_t)n * S2 + lane];
#pragma unroll
    for (int j = 0; j < HID; j++) {
        float tj = __shfl_sync(0xFFFFFFFF, comp[j & 3], j >> 2);
        float wv = (lane < HID) ? __ldg(Wk + j * HID + lane) : 0.f;
        o += tj * wv;
    }
    g_O2[(size_t)n * S2 + lane] = o;
}

// prop30_last: no T store; O2 finalized in-register -> h=relu(O2+b2) -> head.
__global__ void k_prop30_last(const float* __restrict__ hin, const float* __restrict__ Tprev,
                              const float* __restrict__ Wk, const float* __restrict__ b2,
                              const float* __restrict__ Wl, const float* __restrict__ bl,
                              float* __restrict__ out, float scale) {
    int warp = (blockIdx.x * blockDim.x + threadIdx.x) >> 5;
    int lane = threadIdx.x & 31;
    if (warp >= NN) return;
    int n = warp;
    int off = lane & 7;
    int sub = lane >> 3;
    int s = g_rs[n], e = g_rs[n + 1];
    float4 acc = make_float4(0.f, 0.f, 0.f, 0.f);
    int i = s + sub;
    for (; i + 4 < e; i += 8) {
        int2 r0 = g_recs[i], r1 = g_recs[i + 4];
        float c0 = __int_as_float(r0.y) * scale;
        float c1 = __int_as_float(r1.y) * scale;
        float4 v0 = *(const float4*)(hin + ((size_t)r0.x << 5) + (off << 2));
        float4 v1 = *(const float4*)(hin + ((size_t)r1.x << 5) + (off << 2));
        acc.x += c0 * v0.x + c1 * v1.x;
        acc.y += c0 * v0.y + c1 * v1.y;
        acc.z += c0 * v0.z + c1 * v1.z;
        acc.w += c0 * v0.w + c1 * v1.w;
    }
    if (i < e) {
        int2 r = g_recs[i];
        float c = __int_as_float(r.y) * scale;
        float4 v = *(const float4*)(hin + ((size_t)r.x << 5) + (off << 2));
        acc.x += c * v.x; acc.y += c * v.y; acc.z += c * v.z; acc.w += c * v.w;
    }
#pragma unroll
    for (int m = 8; m <= 16; m <<= 1) {
        acc.x += __shfl_xor_sync(0xFFFFFFFF, acc.x, m);
        acc.y += __shfl_xor_sync(0xFFFFFFFF, acc.y, m);
        acc.z += __shfl_xor_sync(0xFFFFFFFF, acc.z, m);
        acc.w += __shfl_xor_sync(0xFFFFFFFF, acc.w, m);
    }
    if (lane < 8) {
        float4 v = *(const float4*)(Tprev + ((size_t)n << 5) + (lane << 2));
        acc.x -= v.x; acc.y -= v.y; acc.z -= v.z; acc.w -= v.w;
    }
    float comp[4] = {acc.x, acc.y, acc.z, acc.w};
    float o = g_O2[(size_t)n * S2 + lane];
#pragma unroll
    for (int j = 0; j < HID; j++) {
        float tj = __shfl_sync(0xFFFFFFFF, comp[j & 3], j >> 2);
        float wv = (lane < HID) ? __ldg(Wk + j * HID + lane) : 0.f;
        o += tj * wv;
    }
    // h = relu(o + b2); head: r[c] = bl[c] + sum_j h_j * Wl[j][c]
    float h = 0.f;
    if (lane < HID) h = fmaxf(o + __ldg(b2 + lane), 0.f);
    float r0 = 0.f, r1 = 0.f, r2 = 0.f, r3 = 0.f;
    if (lane < HID) {
        const float* wl = Wl + lane * NCLS;
        r0 = h * __ldg(wl + 0);
        r1 = h * __ldg(wl + 1);
        r2 = h * __ldg(wl + 2);
        r3 = h * __ldg(wl + 3);
    }
#pragma unroll
    for (int m = 1; m <= 16; m <<= 1) {
        r0 += __shfl_xor_sync(0xFFFFFFFF, r0, m);
        r1 += __shfl_xor_sync(0xFFFFFFFF, r1, m);
        r2 += __shfl_xor_sync(0xFFFFFFFF, r2, m);
        r3 += __shfl_xor_sync(0xFFFFFFFF, r3, m);
    }
    if (lane == 0) {
        r0 += __ldg(bl + 0); r1 += __ldg(bl + 1);
        r2 += __ldg(bl + 2); r3 += __ldg(bl + 3);
        *(float4*)(out + (size_t)n * NCLS) = make_float4(r0, r1, r2, r3);
    }
}

// ---------------- launch -----------------------------------------------------
extern "C" void kernel_launch(void* const* d_in, const int* in_sizes, int n_in,
                              void* d_out, int out_size) {
    const float* x  = (const float*)d_in[0];
    const int*   ei = (const int*)d_in[1];
    const float* ew = (const float*)d_in[2];
    const float* W1 = (const float*)d_in[3];
    const float* b1 = (const float*)d_in[4];
    const float* W2 = (const float*)d_in[5];
    const float* b2 = (const float*)d_in[6];
    const float* Wl = (const float*)d_in[7];
    const float* bl = (const float*)d_in[8];
    float* out = (float*)d_out;

    const int* src = ei;
    const int* dst = ei + NE;

    float *T0, *T1, *T2, *A2, *B2, *C2;
    cudaGetSymbolAddress((void**)&T0, g_T0);
    cudaGetSymbolAddress((void**)&T1, g_T1);
    cudaGetSymbolAddress((void**)&T2, g_T2);
    cudaGetSymbolAddress((void**)&A2, g_A2);
    cudaGetSymbolAddress((void**)&B2, g_B2);
    cudaGetSymbolAddress((void**)&C2, g_C2);

    dim3 blk(256);
    dim3 ng((NN + 255) / 256);
    dim3 eg((NE + 255) / 256);
    dim3 nw((NN * 32 + 255) / 256);   // warp-per-node prop grids

    // CSR build (cnt/deg pre-zeroed by previous replay / static init)
    k_deg<<<eg, blk>>>(src, dst, ew);
    k_scan1<<<SCAN_NB, SCAN_BS>>>();
    k_scan2<<<1, 256>>>();
    k_scan3<<<ng, blk>>>();
    k_normbuild<<<eg, blk>>>(src, dst, ew);

    // ---- layer 1 (dim 10, fp32 rows of 16) ----
    k_l1_init<<<ng, blk>>>(x, W1 + 0 * FIN * HID);
    k_prop10<<<nw, blk>>>(T0, nullptr, T1, W1 + 1 * FIN * HID, 1.0f);       // T1
    k_prop10<<<nw, blk>>>(T1, T0, T2, W1 + 2 * FIN * HID, 2.0f);            // T2
    k_prop10<<<nw, blk>>>(T2, T1, T0, W1 + 3 * FIN * HID, 2.0f);            // T3
    k_prop10_last<<<nw, blk>>>(T0, T2, W1 + 4 * FIN * HID, b1,
                               W2 + 0 * HID * HID, 2.0f);                   // T4 + final

    // ---- layer 2 (dim 30, fp32 rows of 32) ----
    k_prop30<<<nw, blk>>>(A2, nullptr, B2, W2 + 1 * HID * HID, 1.0f);       // T1
    k_prop30<<<nw, blk>>>(B2, A2, C2, W2 + 2 * HID * HID, 2.0f);            // T2
    k_prop30<<<nw, blk>>>(C2, B2, A2, W2 + 3 * HID * HID, 2.0f);            // T3
    k_prop30_last<<<nw, blk>>>(A2, C2, W2 + 4 * HID * HID, b2, Wl, bl,
                               out, 2.0f);                                  // T4 + head
}